// round 14
// baseline (speedup 1.0000x reference)
#include <cuda_runtime.h>
#include <math.h>
#include <stdint.h>

#define NN 200000
#define FF 128
#define EE 600000
#define MAXSLOT 200064   // 1563 * 128
#define SW 4096          // stage words: 128 rows x 32 k
#define BOFF 12288       // B stages word offset (3 * SW)
#define G_SMEM 98304     // (3*SW A + 3*SW B) * 4 bytes

// ---------------- scratch ----------------
__device__ int g_min1[NN];
__device__ int g_min2[NN];
__device__ int g_cnt;
__device__ int g_list[MAXSLOT];
__device__ int g_ln0[MAXSLOT];
__device__ int g_ln1[MAXSLOT];
__device__ __align__(16) float g_w1t[256 * 384];              // tf32-rounded, w1t[n][k]
__device__ __align__(16) float g_w2t[128 * 256];              // tf32-rounded, w2t[n][k]
__device__ __align__(16) float g_hc[(size_t)MAXSLOT * 256];   // compact h (tf32 bits)

// ---------------- helpers ----------------
__device__ __forceinline__ uint32_t tf32r(float f) {
    uint32_t u;
    asm("cvt.rna.tf32.f32 %0, %1;" : "=r"(u) : "f"(f));
    return u;
}
__device__ __forceinline__ void mma8(float* c, const uint32_t* a, const uint32_t* b) {
    asm volatile(
        "mma.sync.aligned.m16n8k8.row.col.f32.tf32.tf32.f32 "
        "{%0,%1,%2,%3}, {%4,%5,%6,%7}, {%8,%9}, {%0,%1,%2,%3};"
        : "+f"(c[0]), "+f"(c[1]), "+f"(c[2]), "+f"(c[3])
        : "r"(a[0]), "r"(a[1]), "r"(a[2]), "r"(a[3]), "r"(b[0]), "r"(b[1]));
}
__device__ __forceinline__ uint32_t sptr(const void* p) {
    uint32_t a;
    asm("{ .reg .u64 t; cvta.to.shared.u64 t, %1; cvt.u32.u64 %0, t; }" : "=r"(a) : "l"(p));
    return a;
}
__device__ __forceinline__ void cp16(uint32_t dst, const void* src) {
    asm volatile("cp.async.ca.shared.global [%0], [%1], 16;" :: "r"(dst), "l"(src) : "memory");
}
#define CP_COMMIT() asm volatile("cp.async.commit_group;" ::: "memory")
#define CP_WAIT1()  asm volatile("cp.async.wait_group 1;" ::: "memory")

// ---------------- setup: init mins + count + weight prep ----------------
__global__ void k_init(const float* __restrict__ w1, const float* __restrict__ w2) {
    int i = blockIdx.x * blockDim.x + threadIdx.x;
    if (i == 0) g_cnt = 0;
    if (i < NN) { g_min1[i] = NN; g_min2[i] = NN; }
    if (i < 256 * 384) {
        int n = i / 384, k = i % 384;
        g_w1t[i] = __uint_as_float(tf32r(w1[k * 256 + n]));
    }
    if (i < 128 * 256) {
        int n = i / 256, k = i % 256;
        g_w2t[i] = __uint_as_float(tf32r(w2[k * 128 + n]));
    }
}
__global__ void k_pass1(const int* __restrict__ ei) {
    int e = blockIdx.x * blockDim.x + threadIdx.x;
    if (e >= EE) return;
    int s = ei[e], d = ei[EE + e];
    if (s != d) { atomicMin(&g_min1[s], d); atomicMin(&g_min1[d], s); }
}
__global__ void k_pass2(const int* __restrict__ ei) {
    int e = blockIdx.x * blockDim.x + threadIdx.x;
    if (e >= EE) return;
    int s = ei[e], d = ei[EE + e];
    if (s != d) {
        if (d != g_min1[s]) atomicMin(&g_min2[s], d);
        if (s != g_min1[d]) atomicMin(&g_min2[d], s);
    }
}

// ---------------- unconditional copy + classify (store not predicated) ---
__global__ void __launch_bounds__(256) k_copyclass(const float* __restrict__ x,
                                                   const int* __restrict__ types,
                                                   float* __restrict__ out) {
    int r = blockIdx.x * 8 + (threadIdx.x >> 5);
    if (r >= NN) return;
    int lane = threadIdx.x & 31;
    // unconditional copy: no dependency on class loads -> full HBM rate
    ((float4*)out)[(size_t)r * 32 + lane] = ((const float4*)x)[(size_t)r * 32 + lane];
    if (lane == 0) {
        int m1 = g_min1[r], m2 = g_min2[r];
        int cls = (types[r] == 1) ? ((m1 < NN && m2 < NN) ? 2 : 1) : 0;
        out[(size_t)NN * FF + r] = (cls == 1) ? 0.5f : 0.f;  // cls==2 overwritten later
        if (cls == 2) {
            int slot = atomicAdd(&g_cnt, 1);
            g_list[slot] = r;
            g_ln0[slot] = m1;
            g_ln1[slot] = m2;
        }
    }
}

// ---------------------------------------------------------------------------
// GEMM1 compact: 32-wide k-chunks (12), 3-stage cp.async, XOR-swizzled stages.
// g_hc[slot] = relu([x[self]|x[n0]|x[n1]] @ w1 + b1); grid (2, 1563).
// ---------------------------------------------------------------------------
__global__ void __launch_bounds__(256, 2) k_gemm1c(const float* __restrict__ x,
                                                   const float* __restrict__ b1) {
    const int r0 = blockIdx.y * 128;
    const int cnt = g_cnt;
    if (r0 >= cnt) return;

    extern __shared__ uint32_t dsm[];
    __shared__ int sSelf[128], sN0[128], sN1[128];

    const int t = threadIdx.x, lane = t & 31, w = t >> 5;
    const int bx = blockIdx.x;

    if (t < 128) {
        int slot = r0 + t;
        bool ok = slot < cnt;
        sSelf[t] = ok ? g_list[slot] : 0;
        sN0[t]   = ok ? g_ln0[slot] : 0;
        sN1[t]   = ok ? g_ln1[slot] : 0;
    }
    __syncthreads();

    const int row = t >> 1, kh2 = (t & 1) * 16;   // staging: thread covers 16 k
    const int mw = w & 3, nw = w >> 2;
    const int gid = lane >> 2, tig = lane & 3;
    const int swz = gid << 2;                      // fragment-read swizzle
    const int rswz = (row & 7) << 2;               // staging-write swizzle
    const uint32_t sbase = sptr(dsm);
    const float* bsrc = g_w1t + (size_t)(bx * 128 + row) * 384 + kh2;

    float acc[2][8][4];
#pragma unroll
    for (int ms = 0; ms < 2; ms++)
#pragma unroll
        for (int nt = 0; nt < 8; nt++)
#pragma unroll
            for (int j = 0; j < 4; j++) acc[ms][nt][j] = 0.f;

    auto issue = [&](int c) {
        const int st = (c % 3) * SW;
        const int sel = c >> 2;
        const int src = (sel == 0) ? sSelf[row] : (sel == 1 ? sN0[row] : sN1[row]);
        const float* ap = x + (size_t)src * 128 + (c & 3) * 32 + kh2;
        const float* bp = bsrc + c * 32;
#pragma unroll
        for (int j = 0; j < 4; j++) {
            uint32_t dA = sbase + (st + row * 32 + ((kh2 + j * 4) ^ rswz)) * 4;
            uint32_t dB = dA + BOFF * 4;
            cp16(dA, ap + j * 4);
            cp16(dB, bp + j * 4);
        }
    };

    issue(0); CP_COMMIT();
    issue(1); CP_COMMIT();

    for (int c = 0; c < 12; c++) {
        CP_WAIT1();
        __syncthreads();
        if (c + 2 < 12) issue(c + 2);
        CP_COMMIT();

        const uint32_t* A = dsm + (c % 3) * SW;
        const uint32_t* B = A + BOFF;
#pragma unroll
        for (int k8 = 0; k8 < 4; k8++) {
            const int kb = k8 * 8;
            const int kL = (kb + tig) ^ swz;
            const int kH = (kb + tig + 4) ^ swz;
            uint32_t af[2][4];
#pragma unroll
            for (int ms = 0; ms < 2; ms++) {
                int m = mw * 32 + ms * 16 + gid;
                af[ms][0] = A[m * 32 + kL];
                af[ms][1] = A[(m + 8) * 32 + kL];
                af[ms][2] = A[m * 32 + kH];
                af[ms][3] = A[(m + 8) * 32 + kH];
            }
#pragma unroll
            for (int nt = 0; nt < 8; nt++) {
                int n = nw * 64 + nt * 8 + gid;
                uint32_t bf[2] = { B[n * 32 + kL], B[n * 32 + kH] };
                mma8(acc[0][nt], af[0], bf);
                mma8(acc[1][nt], af[1], bf);
            }
        }
    }

    // epilogue: bias + relu -> compact h (tf32 rna so GEMM2 A is pre-rounded)
#pragma unroll
    for (int ms = 0; ms < 2; ms++) {
        int sl = r0 + mw * 32 + ms * 16 + gid;
#pragma unroll
        for (int nt = 0; nt < 8; nt++) {
            int col = bx * 128 + nw * 64 + nt * 8 + tig * 2;
            float bb0 = __ldg(&b1[col]), bb1 = __ldg(&b1[col + 1]);
            if (sl < cnt) {
                uint2 v = { tf32r(fmaxf(acc[ms][nt][0] + bb0, 0.f)),
                            tf32r(fmaxf(acc[ms][nt][1] + bb1, 0.f)) };
                *(uint2*)&g_hc[(size_t)sl * 256 + col] = v;
            }
            if (sl + 8 < cnt) {
                uint2 v = { tf32r(fmaxf(acc[ms][nt][2] + bb0, 0.f)),
                            tf32r(fmaxf(acc[ms][nt][3] + bb1, 0.f)) };
                *(uint2*)&g_hc[(size_t)(sl + 8) * 256 + col] = v;
            }
        }
    }
}

// ---------------------------------------------------------------------------
// GEMM2 compact: 32-wide k-chunks (8), 3-stage cp.async, XOR swizzle
// + bias + LN + scatter + fused murray head.
// ---------------------------------------------------------------------------
__global__ void __launch_bounds__(256, 2) k_gemm2c(const float* __restrict__ b2,
                                                   const float* __restrict__ lng,
                                                   const float* __restrict__ lnb,
                                                   const float* __restrict__ mw1,
                                                   const float* __restrict__ mb1,
                                                   const float* __restrict__ mw2,
                                                   const float* __restrict__ mb2,
                                                   float* __restrict__ out) {
    const int r0 = blockIdx.x * 128;
    const int cnt = g_cnt;
    if (r0 >= cnt) return;

    extern __shared__ uint32_t dsm[];
    float* Cst = (float*)dsm;   // aliases stages after mainloop

    __shared__ int   sRow[128];
    __shared__ float sb2[128], slg[128], slb[128];

    const int t = threadIdx.x, lane = t & 31, w = t >> 5;

    if (t < 128) {
        int slot = r0 + t;
        sRow[t] = (slot < cnt) ? g_list[slot] : -1;
        sb2[t] = b2[t]; slg[t] = lng[t]; slb[t] = lnb[t];
    }
    __syncthreads();

    const int row = t >> 1, kh2 = (t & 1) * 16;
    const int aslot = min(r0 + row, cnt - 1);
    const int mw = w & 3, nw = w >> 2;
    const int gid = lane >> 2, tig = lane & 3;
    const int swz = gid << 2;
    const int rswz = (row & 7) << 2;
    const uint32_t sbase = sptr(dsm);
    const float* asrc = g_hc + (size_t)aslot * 256 + kh2;
    const float* bsrc = g_w2t + (size_t)row * 256 + kh2;

    float acc[2][8][4];
#pragma unroll
    for (int ms = 0; ms < 2; ms++)
#pragma unroll
        for (int nt = 0; nt < 8; nt++)
#pragma unroll
            for (int j = 0; j < 4; j++) acc[ms][nt][j] = 0.f;

    auto issue = [&](int c) {
        const int st = (c % 3) * SW;
        const float* ap = asrc + c * 32;
        const float* bp = bsrc + c * 32;
#pragma unroll
        for (int j = 0; j < 4; j++) {
            uint32_t dA = sbase + (st + row * 32 + ((kh2 + j * 4) ^ rswz)) * 4;
            uint32_t dB = dA + BOFF * 4;
            cp16(dA, ap + j * 4);
            cp16(dB, bp + j * 4);
        }
    };

    issue(0); CP_COMMIT();
    issue(1); CP_COMMIT();

    for (int c = 0; c < 8; c++) {
        CP_WAIT1();
        __syncthreads();
        if (c + 2 < 8) issue(c + 2);
        CP_COMMIT();

        const uint32_t* A = dsm + (c % 3) * SW;
        const uint32_t* B = A + BOFF;
#pragma unroll
        for (int k8 = 0; k8 < 4; k8++) {
            const int kb = k8 * 8;
            const int kL = (kb + tig) ^ swz;
            const int kH = (kb + tig + 4) ^ swz;
            uint32_t af[2][4];
#pragma unroll
            for (int ms = 0; ms < 2; ms++) {
                int m = mw * 32 + ms * 16 + gid;
                af[ms][0] = A[m * 32 + kL];
                af[ms][1] = A[(m + 8) * 32 + kL];
                af[ms][2] = A[m * 32 + kH];
                af[ms][3] = A[(m + 8) * 32 + kH];
            }
#pragma unroll
            for (int nt = 0; nt < 8; nt++) {
                int n = nw * 64 + nt * 8 + gid;
                uint32_t bf[2] = { B[n * 32 + kL], B[n * 32 + kH] };
                mma8(acc[0][nt], af[0], bf);
                mma8(acc[1][nt], af[1], bf);
            }
        }
    }
    __syncthreads();   // stage buffers dead; Cst aliases them

    // stage bias-added C
#pragma unroll
    for (int ms = 0; ms < 2; ms++) {
        int rl = mw * 32 + ms * 16 + gid;
#pragma unroll
        for (int nt = 0; nt < 8; nt++) {
            int col = nw * 64 + nt * 8 + tig * 2;
            Cst[rl * 132 + col]           = acc[ms][nt][0] + sb2[col];
            Cst[rl * 132 + col + 1]       = acc[ms][nt][1] + sb2[col + 1];
            Cst[(rl + 8) * 132 + col]     = acc[ms][nt][2] + sb2[col];
            Cst[(rl + 8) * 132 + col + 1] = acc[ms][nt][3] + sb2[col + 1];
        }
    }
    __syncthreads();

    // per-row LayerNorm
    if (t < 128) {
        float* rp = Cst + t * 132;
        float s = 0.f, q = 0.f;
#pragma unroll
        for (int j = 0; j < 32; j++) {
            float4 v = ((const float4*)rp)[j];
            s += v.x + v.y + v.z + v.w;
            q += v.x * v.x + v.y * v.y + v.z * v.z + v.w * v.w;
        }
        float mean = s * (1.f / 128.f);
        float var  = q * (1.f / 128.f) - mean * mean;
        float rs   = rsqrtf(var + 1e-5f);
#pragma unroll
        for (int j = 0; j < 32; j++) {
            float4 v = ((const float4*)rp)[j];
            v.x = (v.x - mean) * rs * slg[4 * j]     + slb[4 * j];
            v.y = (v.y - mean) * rs * slg[4 * j + 1] + slb[4 * j + 1];
            v.z = (v.z - mean) * rs * slg[4 * j + 2] + slb[4 * j + 2];
            v.w = (v.w - mean) * rs * slg[4 * j + 3] + slb[4 * j + 3];
            ((float4*)rp)[j] = v;
        }
    }
    __syncthreads();

    // scatter: out[node] = proc
    {
        float4* o4 = (float4*)out;
        for (int idx = t; idx < 128 * 32; idx += 256) {
            int rl = idx >> 5, c4 = idx & 31;
            int node = sRow[rl];
            if (node >= 0)
                o4[(size_t)node * 32 + c4] = ((const float4*)(Cst + rl * 132))[c4];
        }
    }

    // fused murray head: warp per row, proc from Cst, weights via L1 (__ldg)
    {
        const float bias2 = __ldg(mb2);
        const float mb1a = __ldg(&mb1[2 * lane]);
        const float mb1b = __ldg(&mb1[2 * lane + 1]);
        const float w2a  = __ldg(&mw2[2 * lane]);
        const float w2b  = __ldg(&mw2[2 * lane + 1]);
        float* mo = out + (size_t)NN * FF;
        for (int rl = w; rl < 128; rl += 8) {
            int node = sRow[rl];
            if (node < 0) continue;
            float4 pr = ((const float4*)(Cst + rl * 132))[lane];
            float m0 = mb1a, m1 = mb1b;
#pragma unroll
            for (int k4 = 0; k4 < 32; k4++) {
                float vx = __shfl_sync(0xffffffffu, pr.x, k4);
                float vy = __shfl_sync(0xffffffffu, pr.y, k4);
                float vz = __shfl_sync(0xffffffffu, pr.z, k4);
                float vw = __shfl_sync(0xffffffffu, pr.w, k4);
                float2 w0  = __ldg((const float2*)&mw1[(k4 * 4 + 0) * 64 + 2 * lane]);
                float2 w1v = __ldg((const float2*)&mw1[(k4 * 4 + 1) * 64 + 2 * lane]);
                float2 w2v = __ldg((const float2*)&mw1[(k4 * 4 + 2) * 64 + 2 * lane]);
                float2 w3v = __ldg((const float2*)&mw1[(k4 * 4 + 3) * 64 + 2 * lane]);
                m0 = fmaf(vx, w0.x, fmaf(vy, w1v.x, fmaf(vz, w2v.x, fmaf(vw, w3v.x, m0))));
                m1 = fmaf(vx, w0.y, fmaf(vy, w1v.y, fmaf(vz, w2v.y, fmaf(vw, w3v.y, m1))));
            }
            float p = fmaxf(m0, 0.f) * w2a + fmaxf(m1, 0.f) * w2b;
#pragma unroll
            for (int m = 16; m; m >>= 1) p += __shfl_xor_sync(0xffffffffu, p, m);
            if (lane == 0) mo[node] = 1.f / (1.f + expf(-(p + bias2)));
        }
    }
}

// ---------------------------------------------------------------------------
extern "C" void kernel_launch(void* const* d_in, const int* in_sizes, int n_in,
                              void* d_out, int out_size) {
    const float* x   = (const float*)d_in[0];
    const int*   ei  = (const int*)d_in[1];
    const int*   ty  = (const int*)d_in[2];
    const float* w1  = (const float*)d_in[3];
    const float* b1  = (const float*)d_in[4];
    const float* w2  = (const float*)d_in[5];
    const float* b2  = (const float*)d_in[6];
    const float* lng = (const float*)d_in[7];
    const float* lnb = (const float*)d_in[8];
    const float* mw1 = (const float*)d_in[9];
    const float* mb1 = (const float*)d_in[10];
    const float* mw2 = (const float*)d_in[11];
    const float* mb2 = (const float*)d_in[12];
    float* out = (float*)d_out;

    static bool attr_done = false;
    if (!attr_done) {
        cudaFuncSetAttribute(k_gemm1c, cudaFuncAttributeMaxDynamicSharedMemorySize, G_SMEM);
        cudaFuncSetAttribute(k_gemm2c, cudaFuncAttributeMaxDynamicSharedMemorySize, G_SMEM);
        attr_done = true;
    }

    k_init<<<(NN + 255) / 256, 256>>>(w1, w2);
    k_pass1<<<(EE + 255) / 256, 256>>>(ei);
    k_pass2<<<(EE + 255) / 256, 256>>>(ei);
    k_copyclass<<<(NN + 7) / 8, 256>>>(x, ty, out);

    dim3 g1(2, MAXSLOT / 128);
    k_gemm1c<<<g1, 256, G_SMEM>>>(x, b1);
    k_gemm2c<<<MAXSLOT / 128, 256, G_SMEM>>>(b2, lng, lnb, mw1, mb1, mw2, mb2, out);
}

// round 17
// speedup vs baseline: 1.0389x; 1.0389x over previous
#include <cuda_runtime.h>
#include <math.h>
#include <stdint.h>

#define NN 200000
#define FF 128
#define EE 600000
#define KP 20            // padded smem k-stride (words)
#define MAXSLOT 200064   // 1563 * 128
#define STG_W 2560       // words per stage buffer (128*KP)
#define NSTG 5           // pipeline stages
#define G_SMEM (2 * NSTG * STG_W * 4)   // 102400 B: A stages then B stages

// ---------------- scratch ----------------
__device__ int g_min1[NN];
__device__ int g_min2[NN];
__device__ int g_cnt;
__device__ int g_list[MAXSLOT];
__device__ int g_ln0[MAXSLOT];
__device__ int g_ln1[MAXSLOT];
__device__ __align__(16) float g_w1t[256 * 384];              // tf32-rounded, w1t[n][k]
__device__ __align__(16) float g_w2t[128 * 256];              // tf32-rounded, w2t[n][k]
__device__ __align__(16) float g_hc[(size_t)MAXSLOT * 256];   // compact h (tf32 bits)

// ---------------- helpers ----------------
__device__ __forceinline__ uint32_t tf32r(float f) {
    uint32_t u;
    asm("cvt.rna.tf32.f32 %0, %1;" : "=r"(u) : "f"(f));
    return u;
}
__device__ __forceinline__ void mma8(float* c, const uint32_t* a, const uint32_t* b) {
    asm volatile(
        "mma.sync.aligned.m16n8k8.row.col.f32.tf32.tf32.f32 "
        "{%0,%1,%2,%3}, {%4,%5,%6,%7}, {%8,%9}, {%0,%1,%2,%3};"
        : "+f"(c[0]), "+f"(c[1]), "+f"(c[2]), "+f"(c[3])
        : "r"(a[0]), "r"(a[1]), "r"(a[2]), "r"(a[3]), "r"(b[0]), "r"(b[1]));
}
__device__ __forceinline__ uint32_t sptr(const void* p) {
    uint32_t a;
    asm("{ .reg .u64 t; cvta.to.shared.u64 t, %1; cvt.u32.u64 %0, t; }" : "=r"(a) : "l"(p));
    return a;
}
__device__ __forceinline__ void cp16(uint32_t dst, const void* src) {
    asm volatile("cp.async.ca.shared.global [%0], [%1], 16;" :: "r"(dst), "l"(src) : "memory");
}
#define CP_COMMIT() asm volatile("cp.async.commit_group;" ::: "memory")
#define CP_WAIT3()  asm volatile("cp.async.wait_group 3;" ::: "memory")

// ---------------- setup: init mins + count + weight prep ----------------
__global__ void k_init(const float* __restrict__ w1, const float* __restrict__ w2) {
    int i = blockIdx.x * blockDim.x + threadIdx.x;
    if (i == 0) g_cnt = 0;
    if (i < NN) { g_min1[i] = NN; g_min2[i] = NN; }
    if (i < 256 * 384) {
        int n = i / 384, k = i % 384;
        g_w1t[i] = __uint_as_float(tf32r(w1[k * 256 + n]));
    }
    if (i < 128 * 256) {
        int n = i / 256, k = i % 256;
        g_w2t[i] = __uint_as_float(tf32r(w2[k * 128 + n]));
    }
}
__global__ void k_pass1(const int* __restrict__ ei) {
    int e = blockIdx.x * blockDim.x + threadIdx.x;
    if (e >= EE) return;
    int s = ei[e], d = ei[EE + e];
    if (s != d) { atomicMin(&g_min1[s], d); atomicMin(&g_min1[d], s); }
}
__global__ void k_pass2(const int* __restrict__ ei) {
    int e = blockIdx.x * blockDim.x + threadIdx.x;
    if (e >= EE) return;
    int s = ei[e], d = ei[EE + e];
    if (s != d) {
        if (d != g_min1[s]) atomicMin(&g_min2[s], d);
        if (s != g_min1[d]) atomicMin(&g_min2[d], s);
    }
}

// ---------------- pure copy: out = x (no class work in this kernel!) -----
__global__ void __launch_bounds__(256) k_copy(const float* __restrict__ x,
                                              float* __restrict__ out) {
    int row = blockIdx.x * 8 + (threadIdx.x >> 5);
    if (row >= NN) return;
    int c = threadIdx.x & 31;
    ((float4*)out)[(size_t)row * 32 + c] = ((const float4*)x)[(size_t)row * 32 + c];
}

// ---------------- classify + compact + murray defaults -------------------
__global__ void k_class(const int* __restrict__ types, float* __restrict__ out) {
    int r = blockIdx.x * blockDim.x + threadIdx.x;
    if (r >= NN) return;
    int m1 = g_min1[r], m2 = g_min2[r];
    int cls = (types[r] == 1) ? ((m1 < NN && m2 < NN) ? 2 : 1) : 0;
    out[(size_t)NN * FF + r] = (cls == 1) ? 0.5f : 0.f;  // cls==2 overwritten by gemm2
    if (cls == 2) {
        int slot = atomicAdd(&g_cnt, 1);
        g_list[slot] = r;
        g_ln0[slot] = m1;
        g_ln1[slot] = m2;
    }
}

// ---------------------------------------------------------------------------
// GEMM1 compact, 5-stage cp.async pipeline (prefetch depth 3).
// g_hc[slot] = relu([x[self]|x[n0]|x[n1]] @ w1 + b1)
// grid (2, 1563). 128x128 tile, K=384 in 24 chunks of 16.
// ---------------------------------------------------------------------------
__global__ void __launch_bounds__(256, 2) k_gemm1c(const float* __restrict__ x,
                                                   const float* __restrict__ b1) {
    const int r0 = blockIdx.y * 128;
    const int cnt = g_cnt;
    if (r0 >= cnt) return;

    extern __shared__ uint32_t dsm[];
    __shared__ int sSelf[128], sN0[128], sN1[128];

    const int t = threadIdx.x, lane = t & 31, w = t >> 5;
    const int bx = blockIdx.x;

    if (t < 128) {
        int slot = r0 + t;
        bool ok = slot < cnt;
        sSelf[t] = ok ? g_list[slot] : 0;
        sN0[t]   = ok ? g_ln0[slot] : 0;
        sN1[t]   = ok ? g_ln1[slot] : 0;
    }
    __syncthreads();

    const int row = t >> 1, kh = (t & 1) * 8;
    const int mw = w & 3, nw = w >> 2;
    const int gid = lane >> 2, tig = lane & 3;
    const uint32_t sbase = sptr(dsm);
    const uint32_t adst = sbase + (row * KP + kh) * 4;
    const uint32_t bdst = adst + NSTG * STG_W * 4;
    const float* bsrc = g_w1t + (size_t)(bx * 128 + row) * 384 + kh;

    float acc[2][8][4];
#pragma unroll
    for (int ms = 0; ms < 2; ms++)
#pragma unroll
        for (int nt = 0; nt < 8; nt++)
#pragma unroll
            for (int j = 0; j < 4; j++) acc[ms][nt][j] = 0.f;

    auto issue = [&](int c) {
        const int st = (c % NSTG) * STG_W * 4;
        const int sel = c >> 3;
        const int src = (sel == 0) ? sSelf[row] : (sel == 1 ? sN0[row] : sN1[row]);
        const float* ap = x + (size_t)src * 128 + (c & 7) * 16 + kh;
        cp16(adst + st, ap);
        cp16(adst + st + 16, ap + 4);
        const float* bp = bsrc + c * 16;
        cp16(bdst + st, bp);
        cp16(bdst + st + 16, bp + 4);
    };

    issue(0); CP_COMMIT();
    issue(1); CP_COMMIT();
    issue(2); CP_COMMIT();
    issue(3); CP_COMMIT();

    for (int c = 0; c < 24; c++) {
        CP_WAIT3();
        __syncthreads();
        if (c + 4 < 24) issue(c + 4);
        CP_COMMIT();

        const uint32_t* A = dsm + (c % NSTG) * STG_W;
        const uint32_t* B = A + NSTG * STG_W;
#pragma unroll
        for (int k8 = 0; k8 < 2; k8++) {
            const int kb = k8 * 8;
            uint32_t af[2][4];
#pragma unroll
            for (int ms = 0; ms < 2; ms++) {
                int m = mw * 32 + ms * 16;
                af[ms][0] = A[(m + gid) * KP + kb + tig];
                af[ms][1] = A[(m + 8 + gid) * KP + kb + tig];
                af[ms][2] = A[(m + gid) * KP + kb + tig + 4];
                af[ms][3] = A[(m + 8 + gid) * KP + kb + tig + 4];
            }
#pragma unroll
            for (int nt = 0; nt < 8; nt++) {
                int n = nw * 64 + nt * 8 + gid;
                uint32_t bf[2] = { B[n * KP + kb + tig], B[n * KP + kb + tig + 4] };
                mma8(acc[0][nt], af[0], bf);
                mma8(acc[1][nt], af[1], bf);
            }
        }
    }

    // epilogue: bias + relu -> compact h (tf32 rna so GEMM2 A is pre-rounded)
#pragma unroll
    for (int ms = 0; ms < 2; ms++) {
        int sl = r0 + mw * 32 + ms * 16 + gid;
#pragma unroll
        for (int nt = 0; nt < 8; nt++) {
            int col = bx * 128 + nw * 64 + nt * 8 + tig * 2;
            float bb0 = __ldg(&b1[col]), bb1 = __ldg(&b1[col + 1]);
            if (sl < cnt) {
                uint2 v = { tf32r(fmaxf(acc[ms][nt][0] + bb0, 0.f)),
                            tf32r(fmaxf(acc[ms][nt][1] + bb1, 0.f)) };
                *(uint2*)&g_hc[(size_t)sl * 256 + col] = v;
            }
            if (sl + 8 < cnt) {
                uint2 v = { tf32r(fmaxf(acc[ms][nt][2] + bb0, 0.f)),
                            tf32r(fmaxf(acc[ms][nt][3] + bb1, 0.f)) };
                *(uint2*)&g_hc[(size_t)(sl + 8) * 256 + col] = v;
            }
        }
    }
}

// ---------------------------------------------------------------------------
// GEMM2 compact, 5-stage cp.async pipeline + bias + LN + scatter + murray.
// dyn smem: stages (100 KB) aliased with Cst[128*132] after mainloop.
// ---------------------------------------------------------------------------
__global__ void __launch_bounds__(256, 2) k_gemm2c(const float* __restrict__ b2,
                                                   const float* __restrict__ lng,
                                                   const float* __restrict__ lnb,
                                                   const float* __restrict__ mw1,
                                                   const float* __restrict__ mb1,
                                                   const float* __restrict__ mw2,
                                                   const float* __restrict__ mb2,
                                                   float* __restrict__ out) {
    const int r0 = blockIdx.x * 128;
    const int cnt = g_cnt;
    if (r0 >= cnt) return;

    extern __shared__ uint32_t dsm[];
    float* Cst = (float*)dsm;

    __shared__ int   sRow[128];
    __shared__ float sb2[128], slg[128], slb[128];

    const int t = threadIdx.x, lane = t & 31, w = t >> 5;

    if (t < 128) {
        int slot = r0 + t;
        sRow[t] = (slot < cnt) ? g_list[slot] : -1;
        sb2[t] = b2[t]; slg[t] = lng[t]; slb[t] = lnb[t];
    }
    __syncthreads();

    const int row = t >> 1, kh = (t & 1) * 8;
    const int aslot = min(r0 + row, cnt - 1);
    const int mw = w & 3, nw = w >> 2;
    const int gid = lane >> 2, tig = lane & 3;
    const uint32_t sbase = sptr(dsm);
    const uint32_t adst = sbase + (row * KP + kh) * 4;
    const uint32_t bdst = adst + NSTG * STG_W * 4;
    const float* asrc = g_hc + (size_t)aslot * 256 + kh;
    const float* bsrc = g_w2t + (size_t)row * 256 + kh;

    float acc[2][8][4];
#pragma unroll
    for (int ms = 0; ms < 2; ms++)
#pragma unroll
        for (int nt = 0; nt < 8; nt++)
#pragma unroll
            for (int j = 0; j < 4; j++) acc[ms][nt][j] = 0.f;

    auto issue = [&](int c) {
        const int st = (c % NSTG) * STG_W * 4;
        const float* ap = asrc + c * 16;
        cp16(adst + st, ap);
        cp16(adst + st + 16, ap + 4);
        const float* bp = bsrc + c * 16;
        cp16(bdst + st, bp);
        cp16(bdst + st + 16, bp + 4);
    };

    issue(0); CP_COMMIT();
    issue(1); CP_COMMIT();
    issue(2); CP_COMMIT();
    issue(3); CP_COMMIT();

    for (int c = 0; c < 16; c++) {
        CP_WAIT3();
        __syncthreads();
        if (c + 4 < 16) issue(c + 4);
        CP_COMMIT();

        const uint32_t* A = dsm + (c % NSTG) * STG_W;
        const uint32_t* B = A + NSTG * STG_W;
#pragma unroll
        for (int k8 = 0; k8 < 2; k8++) {
            const int kb = k8 * 8;
            uint32_t af[2][4];
#pragma unroll
            for (int ms = 0; ms < 2; ms++) {
                int m = mw * 32 + ms * 16;
                af[ms][0] = A[(m + gid) * KP + kb + tig];
                af[ms][1] = A[(m + 8 + gid) * KP + kb + tig];
                af[ms][2] = A[(m + gid) * KP + kb + tig + 4];
                af[ms][3] = A[(m + 8 + gid) * KP + kb + tig + 4];
            }
#pragma unroll
            for (int nt = 0; nt < 8; nt++) {
                int n = nw * 64 + nt * 8 + gid;
                uint32_t bf[2] = { B[n * KP + kb + tig], B[n * KP + kb + tig + 4] };
                mma8(acc[0][nt], af[0], bf);
                mma8(acc[1][nt], af[1], bf);
            }
        }
    }
    __syncthreads();   // stage buffers dead; Cst aliases them

    // stage bias-added C
#pragma unroll
    for (int ms = 0; ms < 2; ms++) {
        int rl = mw * 32 + ms * 16 + gid;
#pragma unroll
        for (int nt = 0; nt < 8; nt++) {
            int col = nw * 64 + nt * 8 + tig * 2;
            Cst[rl * 132 + col]           = acc[ms][nt][0] + sb2[col];
            Cst[rl * 132 + col + 1]       = acc[ms][nt][1] + sb2[col + 1];
            Cst[(rl + 8) * 132 + col]     = acc[ms][nt][2] + sb2[col];
            Cst[(rl + 8) * 132 + col + 1] = acc[ms][nt][3] + sb2[col + 1];
        }
    }
    __syncthreads();

    // per-row LayerNorm
    if (t < 128) {
        float* rp = Cst + t * 132;
        float s = 0.f, q = 0.f;
#pragma unroll
        for (int j = 0; j < 32; j++) {
            float4 v = ((const float4*)rp)[j];
            s += v.x + v.y + v.z + v.w;
            q += v.x * v.x + v.y * v.y + v.z * v.z + v.w * v.w;
        }
        float mean = s * (1.f / 128.f);
        float var  = q * (1.f / 128.f) - mean * mean;
        float rs   = rsqrtf(var + 1e-5f);
#pragma unroll
        for (int j = 0; j < 32; j++) {
            float4 v = ((const float4*)rp)[j];
            v.x = (v.x - mean) * rs * slg[4 * j]     + slb[4 * j];
            v.y = (v.y - mean) * rs * slg[4 * j + 1] + slb[4 * j + 1];
            v.z = (v.z - mean) * rs * slg[4 * j + 2] + slb[4 * j + 2];
            v.w = (v.w - mean) * rs * slg[4 * j + 3] + slb[4 * j + 3];
            ((float4*)rp)[j] = v;
        }
    }
    __syncthreads();

    // scatter: out[node] = proc
    {
        float4* o4 = (float4*)out;
        for (int idx = t; idx < 128 * 32; idx += 256) {
            int rl = idx >> 5, c4 = idx & 31;
            int node = sRow[rl];
            if (node >= 0)
                o4[(size_t)node * 32 + c4] = ((const float4*)(Cst + rl * 132))[c4];
        }
    }

    // fused murray head: warp per row, proc from Cst, weights via L1 (__ldg)
    {
        const float bias2 = __ldg(mb2);
        const float mb1a = __ldg(&mb1[2 * lane]);
        const float mb1b = __ldg(&mb1[2 * lane + 1]);
        const float w2a  = __ldg(&mw2[2 * lane]);
        const float w2b  = __ldg(&mw2[2 * lane + 1]);
        float* mo = out + (size_t)NN * FF;
        for (int rl = w; rl < 128; rl += 8) {
            int node = sRow[rl];
            if (node < 0) continue;
            float4 pr = ((const float4*)(Cst + rl * 132))[lane];
            float m0 = mb1a, m1 = mb1b;
#pragma unroll
            for (int k4 = 0; k4 < 32; k4++) {
                float vx = __shfl_sync(0xffffffffu, pr.x, k4);
                float vy = __shfl_sync(0xffffffffu, pr.y, k4);
                float vz = __shfl_sync(0xffffffffu, pr.z, k4);
                float vw = __shfl_sync(0xffffffffu, pr.w, k4);
                float2 w0  = __ldg((const float2*)&mw1[(k4 * 4 + 0) * 64 + 2 * lane]);
                float2 w1v = __ldg((const float2*)&mw1[(k4 * 4 + 1) * 64 + 2 * lane]);
                float2 w2v = __ldg((const float2*)&mw1[(k4 * 4 + 2) * 64 + 2 * lane]);
                float2 w3v = __ldg((const float2*)&mw1[(k4 * 4 + 3) * 64 + 2 * lane]);
                m0 = fmaf(vx, w0.x, fmaf(vy, w1v.x, fmaf(vz, w2v.x, fmaf(vw, w3v.x, m0))));
                m1 = fmaf(vx, w0.y, fmaf(vy, w1v.y, fmaf(vz, w2v.y, fmaf(vw, w3v.y, m1))));
            }
            float p = fmaxf(m0, 0.f) * w2a + fmaxf(m1, 0.f) * w2b;
#pragma unroll
            for (int m = 16; m; m >>= 1) p += __shfl_xor_sync(0xffffffffu, p, m);
            if (lane == 0) mo[node] = 1.f / (1.f + expf(-(p + bias2)));
        }
    }
}

// ---------------------------------------------------------------------------
extern "C" void kernel_launch(void* const* d_in, const int* in_sizes, int n_in,
                              void* d_out, int out_size) {
    const float* x   = (const float*)d_in[0];
    const int*   ei  = (const int*)d_in[1];
    const int*   ty  = (const int*)d_in[2];
    const float* w1  = (const float*)d_in[3];
    const float* b1  = (const float*)d_in[4];
    const float* w2  = (const float*)d_in[5];
    const float* b2  = (const float*)d_in[6];
    const float* lng = (const float*)d_in[7];
    const float* lnb = (const float*)d_in[8];
    const float* mw1 = (const float*)d_in[9];
    const float* mb1 = (const float*)d_in[10];
    const float* mw2 = (const float*)d_in[11];
    const float* mb2 = (const float*)d_in[12];
    float* out = (float*)d_out;

    static bool attr_done = false;
    if (!attr_done) {
        cudaFuncSetAttribute(k_gemm1c, cudaFuncAttributeMaxDynamicSharedMemorySize, G_SMEM);
        cudaFuncSetAttribute(k_gemm2c, cudaFuncAttributeMaxDynamicSharedMemorySize, G_SMEM);
        attr_done = true;
    }

    k_init<<<(NN + 255) / 256, 256>>>(w1, w2);
    k_pass1<<<(EE + 255) / 256, 256>>>(ei);
    k_pass2<<<(EE + 255) / 256, 256>>>(ei);
    k_copy<<<(NN + 7) / 8, 256>>>(x, out);
    k_class<<<(NN + 255) / 256, 256>>>(ty, out);

    dim3 g1(2, MAXSLOT / 128);
    k_gemm1c<<<g1, 256, G_SMEM>>>(x, b1);
    k_gemm2c<<<MAXSLOT / 128, 256, G_SMEM>>>(b2, lng, lnb, mw1, mb1, mw2, mb2, out);
}